// round 14
// baseline (speedup 1.0000x reference)
#include <cuda_runtime.h>
#include <cstdint>

#define NN 100000
#define EE 1600000
#define RR 6
#define CIN 8
#define COUT 16
#define CHUNK 1024

typedef unsigned long long u64;

__device__ int    g_counts[NN];
__device__ int    g_rowstart[NN + 1];
__device__ int    g_cursor[NN];
__device__ int2   g_sd[EE];        // decoded (src, dst) int32
__device__ int2   g_pp[EE];        // dst-sorted (src, edge_id)
__device__ int    g_bsum[128];
__device__ int    g_dhist[64];     // degree histogram (capped at 63)
__device__ int    g_dcur[64];
__device__ int    g_order[NN];     // nodes sorted by degree
__device__ float2 g_phase[CIN * COUT];
__device__ int    g_is64;

// ---- f32x2 packed helpers (sm_10x FFMA2 path) ------------------------------
__device__ __forceinline__ u64 pk2(float lo, float hi) {
    u64 r; asm("mov.b64 %0, {%1, %2};" : "=l"(r) : "f"(lo), "f"(hi)); return r;
}
__device__ __forceinline__ void upk2(float& lo, float& hi, u64 v) {
    asm("mov.b64 {%0, %1}, %2;" : "=f"(lo), "=f"(hi) : "l"(v));
}
__device__ __forceinline__ void ffma2(u64& d, u64 a, u64 b) {
    asm("fma.rn.f32x2 %0, %1, %2, %0;" : "+l"(d) : "l"(a), "l"(b));
}

// ---------------------------------------------------------------------------
// K1: detect int64-vs-int32 edges, zero histograms, precompute phase
__global__ void k_init(const float* __restrict__ offset,
                       const unsigned int* __restrict__ words, int n) {
    int i = blockIdx.x * blockDim.x + threadIdx.x;
    if (i == 0) {
        int any = 0;
        for (int k = 1; k < 512; k += 2) any |= (words[k] != 0u);
        g_is64 = any ? 0 : 1;
    }
    if (i < 64) g_dhist[i] = 0;
    if (i < CIN * COUT) {
        float o = offset[i];
        g_phase[i] = make_float2(cosf(o), sinf(o));
    }
    if (i < n) g_counts[i] = 0;
}

// K2: decode edges once to int2 + histogram of destination degrees
__global__ void k_hist(const char* __restrict__ edges, int E) {
    int e = blockIdx.x * blockDim.x + threadIdx.x;
    if (e >= E) return;
    int src, dst;
    if (g_is64) {
        longlong2 v = ((const longlong2*)edges)[e];
        src = (int)v.x; dst = (int)v.y;
    } else {
        int2 v = ((const int2*)edges)[e];
        src = v.x; dst = v.y;
    }
    g_sd[e] = make_int2(src, dst);
    atomicAdd(&g_counts[dst], 1);
}

// K3a: per-block scan of CHUNK=1024 counts + degree histogram
__global__ void k_scan1(int n) {
    __shared__ int ws[8];
    int b = blockIdx.x, t = threadIdx.x;
    int base = b * CHUNK + t * 4;
    int v0 = 0, v1 = 0, v2 = 0, v3 = 0;
    if (base + 0 < n) { v0 = g_counts[base + 0]; atomicAdd(&g_dhist[min(v0, 63)], 1); }
    if (base + 1 < n) { v1 = g_counts[base + 1]; atomicAdd(&g_dhist[min(v1, 63)], 1); }
    if (base + 2 < n) { v2 = g_counts[base + 2]; atomicAdd(&g_dhist[min(v2, 63)], 1); }
    if (base + 3 < n) { v3 = g_counts[base + 3]; atomicAdd(&g_dhist[min(v3, 63)], 1); }
    int tot = v0 + v1 + v2 + v3;
    int lane = t & 31, wid = t >> 5;
    int s = tot;
#pragma unroll
    for (int off = 1; off < 32; off <<= 1) {
        int u = __shfl_up_sync(0xffffffffu, s, off);
        if (lane >= off) s += u;
    }
    if (lane == 31) ws[wid] = s;
    __syncthreads();
    int add = 0;
#pragma unroll
    for (int w = 0; w < 7; w++) if (w < wid) add += ws[w];
    int run = add + s - tot;
    if (base + 0 < n) { g_rowstart[base + 0] = run; run += v0; }
    if (base + 1 < n) { g_rowstart[base + 1] = run; run += v1; }
    if (base + 2 < n) { g_rowstart[base + 2] = run; run += v2; }
    if (base + 3 < n) { g_rowstart[base + 3] = run; run += v3; }
    if (t == 255) g_bsum[b] = add + s;
}

// K3b: fused block-offset apply (256 indices/block, aligned inside one chunk)
__global__ void k_scan2(int n, int E) {
    __shared__ int s_off;
    int t = threadIdx.x;
    int i0 = blockIdx.x * 256;
    int cid = i0 / CHUNK;
    if (t < 32) {
        int acc = 0;
        for (int j = t; j < cid; j += 32) acc += g_bsum[j];
#pragma unroll
        for (int off = 16; off > 0; off >>= 1)
            acc += __shfl_down_sync(0xffffffffu, acc, off);
        if (t == 0) s_off = acc;
    }
    __syncthreads();
    int i = i0 + t;
    if (i < n) {
        int v = g_rowstart[i] + s_off;
        g_rowstart[i] = v;
        g_cursor[i] = v;
    }
    if (i == 0) g_rowstart[n] = E;
}

// K3c: exclusive scan of the 64-bin degree histogram -> cursors
__global__ void k_dscan() {
    __shared__ int w0tot;
    int t = threadIdx.x;           // 64 threads
    int v = g_dhist[t];
    int lane = t & 31;
    int s = v;
#pragma unroll
    for (int off = 1; off < 32; off <<= 1) {
        int u = __shfl_up_sync(0xffffffffu, s, off);
        if (lane >= off) s += u;
    }
    if (t == 31) w0tot = s;
    __syncthreads();
    int ex = s - v + ((t >= 32) ? w0tot : 0);
    g_dcur[t] = ex;
}

// K3d: scatter node ids into degree-sorted order
__global__ void k_order(int n) {
    int i = blockIdx.x * blockDim.x + threadIdx.x;
    if (i >= n) return;
    int deg = g_rowstart[i + 1] - g_rowstart[i];
    int pos = atomicAdd(&g_dcur[min(deg, 63)], 1);
    g_order[pos] = i;
}

// K4: scatter packed (src, edge) 8B into dst-sorted order
__global__ void k_scatter(int E) {
    int e = blockIdx.x * blockDim.x + threadIdx.x;
    if (e >= E) return;
    int2 sd = g_sd[e];
    int pos = atomicAdd(&g_cursor[sd.y], 1);
    g_pp[pos] = make_int2(sd.x, e);
}

// Packed-pair accumulate: acc[r*8+c] = {ar,ai} += {sr,si} * {x,x}  (FFMA2)
__device__ __forceinline__ void accum2(float4 s0, float4 s1, float4 s2,
                                       float4 xa, float4 xb, u64* acc) {
    u64 spr[RR] = {pk2(s0.x, s0.y), pk2(s0.z, s0.w), pk2(s1.x, s1.y),
                   pk2(s1.z, s1.w), pk2(s2.x, s2.y), pk2(s2.z, s2.w)};
    float xv[CIN] = {xa.x, xa.y, xa.z, xa.w, xb.x, xb.y, xb.z, xb.w};
    u64 xd[CIN];
#pragma unroll
    for (int c = 0; c < CIN; c++) xd[c] = pk2(xv[c], xv[c]);
#pragma unroll
    for (int r = 0; r < RR; r++)
#pragma unroll
        for (int c = 0; c < CIN; c++) ffma2(acc[r * CIN + c], spr[r], xd[c]);
}

// K5: one thread per node (degree-sorted order), unroll-4, f32x2 math
__global__ void __launch_bounds__(128)
k_node(const float* __restrict__ x, const float* __restrict__ sten,
       const float* __restrict__ weight, const float* __restrict__ bias,
       float* __restrict__ out, int n_nodes) {
    __shared__ u64    swp[RR * CIN * COUT];   // (w,w) pairs, 6KB
    __shared__ float2 sp[CIN * COUT];
    __shared__ float  sb[COUT];
    int t = threadIdx.x;
    for (int i = t; i < RR * CIN * COUT; i += 128) {
        float w = weight[i];
        swp[i] = pk2(w, w);
    }
    sp[t] = g_phase[t];
    if (t < COUT) sb[t] = bias[t];
    __syncthreads();

    int idx = blockIdx.x * 128 + t;
    if (idx >= n_nodes) return;
    int n = g_order[idx];

    u64 acc[RR * CIN];
#pragma unroll
    for (int k = 0; k < RR * CIN; k++) acc[k] = 0ull;

    int beg = g_rowstart[n];
    int end = g_rowstart[n + 1];

    int i = beg;
    for (; i + 4 <= end; i += 4) {
        int2 p0 = g_pp[i + 0];
        int2 p1 = g_pp[i + 1];
        int2 p2 = g_pp[i + 2];
        int2 p3 = g_pp[i + 3];
        const float4* sA = (const float4*)(sten + (size_t)p0.y * 12);
        const float4* sB = (const float4*)(sten + (size_t)p1.y * 12);
        const float4* sC = (const float4*)(sten + (size_t)p2.y * 12);
        const float4* sD = (const float4*)(sten + (size_t)p3.y * 12);
        const float4* xA = (const float4*)(x + (size_t)p0.x * CIN);
        const float4* xB = (const float4*)(x + (size_t)p1.x * CIN);
        const float4* xC = (const float4*)(x + (size_t)p2.x * CIN);
        const float4* xD = (const float4*)(x + (size_t)p3.x * CIN);
        float4 a0 = sA[0], a1 = sA[1], a2 = sA[2];
        float4 b0 = sB[0], b1 = sB[1], b2 = sB[2];
        float4 c0 = sC[0], c1 = sC[1], c2 = sC[2];
        float4 d0 = sD[0], d1 = sD[1], d2 = sD[2];
        float4 xa0 = xA[0], xa1 = xA[1];
        float4 xb0 = xB[0], xb1 = xB[1];
        float4 xc0 = xC[0], xc1 = xC[1];
        float4 xd0 = xD[0], xd1 = xD[1];
        accum2(a0, a1, a2, xa0, xa1, acc);
        accum2(b0, b1, b2, xb0, xb1, acc);
        accum2(c0, c1, c2, xc0, xc1, acc);
        accum2(d0, d1, d2, xd0, xd1, acc);
    }
    for (; i < end; i++) {
        int2 p0 = g_pp[i];
        const float4* sA = (const float4*)(sten + (size_t)p0.y * 12);
        float4 a0 = sA[0], a1 = sA[1], a2 = sA[2];
        const float4* xA = (const float4*)(x + (size_t)p0.x * CIN);
        accum2(a0, a1, a2, xA[0], xA[1], acc);
    }

    // y[o] = sum_c phase[c,o] * (sum_r acc[r,c] * w[r,c,o]); magnitude gate
    float2* o2 = (float2*)out;
#pragma unroll 4
    for (int o = 0; o < COUT; o++) {
        float yr = 0.f, yi = 0.f;
#pragma unroll
        for (int c = 0; c < CIN; c++) {
            u64 tp = 0ull;
#pragma unroll
            for (int r = 0; r < RR; r++)
                ffma2(tp, acc[r * CIN + c], swp[(r * CIN + c) * COUT + o]);
            float tr, ti;
            upk2(tr, ti, tp);
            float2 ph = sp[c * COUT + o];
            yr += tr * ph.x - ti * ph.y;
            yi += tr * ph.y + ti * ph.x;
        }
        float mag = sqrtf(yr * yr + yi * yi);
        float sc = fmaxf(mag + sb[o], 0.f) / (mag + 1e-8f);
        o2[(size_t)n * COUT + o] = make_float2(yr * sc, yi * sc);
    }
}

extern "C" void kernel_launch(void* const* d_in, const int* in_sizes, int n_in,
                              void* d_out, int out_size) {
    const float* x      = (const float*)d_in[0];
    const char*  edges  = (const char*)d_in[1];
    const float* sten   = (const float*)d_in[2];
    const float* weight = (const float*)d_in[3];
    const float* offset = (const float*)d_in[4];
    const float* bias   = (const float*)d_in[5];
    float*       out    = (float*)d_out;

    int E = in_sizes[1] / 2;
    int n = in_sizes[0] / CIN;

    k_init<<<(n + 255) / 256, 256>>>(offset, (const unsigned int*)edges, n);
    k_hist<<<(E + 255) / 256, 256>>>(edges, E);
    int nb = (n + CHUNK - 1) / CHUNK;
    k_scan1<<<nb, 256>>>(n);
    k_scan2<<<(n + 255) / 256, 256>>>(n, E);
    k_dscan<<<1, 64>>>();
    k_order<<<(n + 255) / 256, 256>>>(n);
    k_scatter<<<(E + 255) / 256, 256>>>(E);
    k_node<<<(n + 127) / 128, 128>>>(x, sten, weight, bias, out, n);
}

// round 15
// speedup vs baseline: 1.4593x; 1.4593x over previous
#include <cuda_runtime.h>
#include <cstdint>

#define NN 100000
#define EE 1600000
#define RR 6
#define CIN 8
#define COUT 16
#define CHUNK 1024

__device__ int  g_counts[NN];      // zero at load; self-cleaned by k_scan
__device__ int  g_rowstart[NN + 1];
__device__ int  g_cursor[NN];
__device__ int2 g_sd[EE];          // decoded (src, dst) int32
__device__ int2 g_pp[EE];          // dst-sorted (src, edge_id)
__device__ int  g_scanstat[128];   // lookback status: (sum<<2)|flag

// ---------------------------------------------------------------------------
// K1: per-block is64 detect + decode edges to int2 + dst-degree histogram.
// Block 0 also zeroes the scan status flags (runs strictly before k_scan).
__global__ void k_hist(const char* __restrict__ edges, int E) {
    __shared__ int s_is64;
    int t = threadIdx.x;
    if (t == 0) {
        // int64 ids < 2^31 -> high words all zero; int32 -> odd words are ids
        const unsigned int* w = (const unsigned int*)edges;
        int any = 0;
#pragma unroll
        for (int k = 1; k < 64; k += 2) any |= (w[k] != 0u);
        s_is64 = any ? 0 : 1;
    }
    if (blockIdx.x == 0 && t < 128) g_scanstat[t] = 0;
    __syncthreads();
    int e = blockIdx.x * blockDim.x + t;
    if (e >= E) return;
    int src, dst;
    if (s_is64) {
        longlong2 v = ((const longlong2*)edges)[e];
        src = (int)v.x; dst = (int)v.y;
    } else {
        int2 v = ((const int2*)edges)[e];
        src = v.x; dst = v.y;
    }
    g_sd[e] = make_int2(src, dst);
    atomicAdd(&g_counts[dst], 1);
}

// K2: single-pass decoupled-lookback exclusive scan of g_counts ->
// g_rowstart/g_cursor. Also zeroes g_counts (restores launch invariant).
// Grid = 98 blocks <= 148 SMs: all resident, lookback cannot deadlock.
__global__ void k_scan(int n, int E) {
    __shared__ int ws[8];
    __shared__ int s_agg;
    __shared__ int s_prev;
    int b = blockIdx.x, t = threadIdx.x;
    int base = b * CHUNK + t * 4;
    int v0 = 0, v1 = 0, v2 = 0, v3 = 0;
    if (base + 0 < n) v0 = g_counts[base + 0];
    if (base + 1 < n) v1 = g_counts[base + 1];
    if (base + 2 < n) v2 = g_counts[base + 2];
    if (base + 3 < n) v3 = g_counts[base + 3];
    int tot = v0 + v1 + v2 + v3;
    int lane = t & 31, wid = t >> 5;
    int s = tot;
#pragma unroll
    for (int off = 1; off < 32; off <<= 1) {
        int u = __shfl_up_sync(0xffffffffu, s, off);
        if (lane >= off) s += u;
    }
    if (lane == 31) ws[wid] = s;
    __syncthreads();
    int add = 0;
#pragma unroll
    for (int w = 0; w < 7; w++) if (w < wid) add += ws[w];

    // publish aggregate (or inclusive for block 0)
    if (t == 255) {
        int agg = add + s;
        s_agg = agg;
        __threadfence();
        atomicExch(&g_scanstat[b], (agg << 2) | (b == 0 ? 2 : 1));
    }
    __syncthreads();

    // lookback (thread 0)
    if (t == 0) {
        int prev = 0;
        if (b > 0) {
            int j = b - 1;
            while (j >= 0) {
                int st;
                do { st = atomicAdd(&g_scanstat[j], 0); } while ((st & 3) == 0);
                prev += (st >> 2);
                if ((st & 3) == 2) break;
                j--;
            }
            atomicExch(&g_scanstat[b], ((prev + s_agg) << 2) | 2);
        }
        s_prev = prev;
    }
    __syncthreads();

    int run = s_prev + add + s - tot;  // exclusive global prefix
    if (base + 0 < n) { g_rowstart[base + 0] = run; g_cursor[base + 0] = run; run += v0; g_counts[base + 0] = 0; }
    if (base + 1 < n) { g_rowstart[base + 1] = run; g_cursor[base + 1] = run; run += v1; g_counts[base + 1] = 0; }
    if (base + 2 < n) { g_rowstart[base + 2] = run; g_cursor[base + 2] = run; run += v2; g_counts[base + 2] = 0; }
    if (base + 3 < n) { g_rowstart[base + 3] = run; g_cursor[base + 3] = run; run += v3; g_counts[base + 3] = 0; }
    if (b == (int)gridDim.x - 1 && t == 0) g_rowstart[n] = E;
}

// K3: scatter packed (src, edge) 8B into dst-sorted order
__global__ void k_scatter(int E) {
    int e = blockIdx.x * blockDim.x + threadIdx.x;
    if (e >= E) return;
    int2 sd = g_sd[e];
    int pos = atomicAdd(&g_cursor[sd.y], 1);
    g_pp[pos] = make_int2(sd.x, e);
}

__device__ __forceinline__ void accum(float4 s0, float4 s1, float4 s2,
                                      float4 xa, float4 xb,
                                      float* ar, float* ai) {
    float sr[RR]  = {s0.x, s0.z, s1.x, s1.z, s2.x, s2.z};
    float si[RR]  = {s0.y, s0.w, s1.y, s1.w, s2.y, s2.w};
    float xv[CIN] = {xa.x, xa.y, xa.z, xa.w, xb.x, xb.y, xb.z, xb.w};
#pragma unroll
    for (int r = 0; r < RR; r++) {
#pragma unroll
        for (int c = 0; c < CIN; c++) {
            ar[r * CIN + c] += sr[r] * xv[c];
            ai[r * CIN + c] += si[r] * xv[c];
        }
    }
}

// K4: one thread per node, unroll-4 (4 independent pp/sten/x load groups in
// flight), 128 threads/block. Phase computed in-prologue (cos/sin of offset).
__global__ void __launch_bounds__(128)
k_node(const float* __restrict__ x, const float* __restrict__ sten,
       const float* __restrict__ weight, const float* __restrict__ offset,
       const float* __restrict__ bias, float* __restrict__ out, int n_nodes) {
    __shared__ float  sw[RR * CIN * COUT];
    __shared__ float2 sp[CIN * COUT];
    __shared__ float  sb[COUT];
    int t = threadIdx.x;
    for (int i = t; i < RR * CIN * COUT; i += 128) sw[i] = weight[i];
    {
        float o = offset[t];                  // t in [0,128) == CIN*COUT
        sp[t] = make_float2(cosf(o), sinf(o));
    }
    if (t < COUT) sb[t] = bias[t];
    __syncthreads();

    int n = blockIdx.x * 128 + t;
    if (n >= n_nodes) return;

    float ar[RR * CIN], ai[RR * CIN];
#pragma unroll
    for (int k = 0; k < RR * CIN; k++) { ar[k] = 0.f; ai[k] = 0.f; }

    int beg = g_rowstart[n];
    int end = g_rowstart[n + 1];

    int i = beg;
    for (; i + 4 <= end; i += 4) {
        int2 p0 = g_pp[i + 0];
        int2 p1 = g_pp[i + 1];
        int2 p2 = g_pp[i + 2];
        int2 p3 = g_pp[i + 3];
        const float4* sA = (const float4*)(sten + (size_t)p0.y * 12);
        const float4* sB = (const float4*)(sten + (size_t)p1.y * 12);
        const float4* sC = (const float4*)(sten + (size_t)p2.y * 12);
        const float4* sD = (const float4*)(sten + (size_t)p3.y * 12);
        const float4* xA = (const float4*)(x + (size_t)p0.x * CIN);
        const float4* xB = (const float4*)(x + (size_t)p1.x * CIN);
        const float4* xC = (const float4*)(x + (size_t)p2.x * CIN);
        const float4* xD = (const float4*)(x + (size_t)p3.x * CIN);
        float4 a0 = sA[0], a1 = sA[1], a2 = sA[2];
        float4 b0 = sB[0], b1 = sB[1], b2 = sB[2];
        float4 c0 = sC[0], c1 = sC[1], c2 = sC[2];
        float4 d0 = sD[0], d1 = sD[1], d2 = sD[2];
        float4 xa0 = xA[0], xa1 = xA[1];
        float4 xb0 = xB[0], xb1 = xB[1];
        float4 xc0 = xC[0], xc1 = xC[1];
        float4 xd0 = xD[0], xd1 = xD[1];
        accum(a0, a1, a2, xa0, xa1, ar, ai);
        accum(b0, b1, b2, xb0, xb1, ar, ai);
        accum(c0, c1, c2, xc0, xc1, ar, ai);
        accum(d0, d1, d2, xd0, xd1, ar, ai);
    }
    for (; i < end; i++) {
        int2 p0 = g_pp[i];
        const float4* sA = (const float4*)(sten + (size_t)p0.y * 12);
        float4 a0 = sA[0], a1 = sA[1], a2 = sA[2];
        const float4* xA = (const float4*)(x + (size_t)p0.x * CIN);
        accum(a0, a1, a2, xA[0], xA[1], ar, ai);
    }

    // y[o] = sum_c phase[c,o] * (sum_r agg[r,c] * w[r,c,o]); magnitude gate
    float2* o2 = (float2*)out;
#pragma unroll 4
    for (int o = 0; o < COUT; o++) {
        float yr = 0.f, yi = 0.f;
#pragma unroll
        for (int c = 0; c < CIN; c++) {
            float tr = 0.f, ti = 0.f;
#pragma unroll
            for (int r = 0; r < RR; r++) {
                float w = sw[(r * CIN + c) * COUT + o];
                tr += ar[r * CIN + c] * w;
                ti += ai[r * CIN + c] * w;
            }
            float2 ph = sp[c * COUT + o];
            yr += tr * ph.x - ti * ph.y;
            yi += tr * ph.y + ti * ph.x;
        }
        float mag = sqrtf(yr * yr + yi * yi);
        float sc = fmaxf(mag + sb[o], 0.f) / (mag + 1e-8f);
        o2[(size_t)n * COUT + o] = make_float2(yr * sc, yi * sc);
    }
}

extern "C" void kernel_launch(void* const* d_in, const int* in_sizes, int n_in,
                              void* d_out, int out_size) {
    const float* x      = (const float*)d_in[0];
    const char*  edges  = (const char*)d_in[1];
    const float* sten   = (const float*)d_in[2];
    const float* weight = (const float*)d_in[3];
    const float* offset = (const float*)d_in[4];
    const float* bias   = (const float*)d_in[5];
    float*       out    = (float*)d_out;

    int E = in_sizes[1] / 2;
    int n = in_sizes[0] / CIN;
    int nb = (n + CHUNK - 1) / CHUNK;   // 98 <= 148: lookback-safe

    k_hist<<<(E + 255) / 256, 256>>>(edges, E);
    k_scan<<<nb, 256>>>(n, E);
    k_scatter<<<(E + 255) / 256, 256>>>(E);
    k_node<<<(n + 127) / 128, 128>>>(x, sten, weight, offset, bias, out, n);
}